// round 10
// baseline (speedup 1.0000x reference)
#include <cuda_runtime.h>
#include <cstdint>

// Problem constants (fixed by the dataset).
#define NN 100000
#define EE 1600000
#define EPE (EE + NN)          // edges incl. self-loops
#define NEG_SLOPE 0.2f
#define NB 98                  // scan blocks: ceil(100000/1024)
#define DETECT_SAMPLES 65536

// ---------------------------------------------------------------------------
// Scratch (static device globals; no allocations allowed).
// ---------------------------------------------------------------------------
__device__ float g_xl1[(size_t)NN * 64];
__device__ float g_xr1[(size_t)NN * 64];
__device__ float g_agg1[(size_t)NN * 64];    // layer1 output (pre bias/relu)
__device__ float g_xl2[(size_t)NN * 256];
__device__ float g_xr2[(size_t)NN * 256];
__device__ int   g_ssrc[EPE];                // srcs sorted by dst (CSR payload)
__device__ int   g_deg[NN], g_cur[NN];
__device__ int   g_off[NN + 1];              // CSR row offsets
__device__ int   g_bsum[NB];
__device__ int   g_not64;                    // 1 if edge_index buffer is int32

typedef unsigned long long u64;
__device__ __forceinline__ u64 pack2(float x, float y) {
    u64 r; asm("mov.b64 %0, {%1,%2};" : "=l"(r) : "f"(x), "f"(y)); return r;
}
__device__ __forceinline__ u64 ffma2(u64 a, u64 b, u64 c) {
    u64 d; asm("fma.rn.f32x2 %0, %1, %2, %3;" : "=l"(d) : "l"(a), "l"(b), "l"(c)); return d;
}
__device__ __forceinline__ float2 unpack2(u64 v) {
    float2 f; asm("mov.b64 {%0,%1}, %2;" : "=f"(f.x), "=f"(f.y) : "l"(v)); return f;
}
__device__ __forceinline__ float lrelu(float v) { return v > 0.f ? v : NEG_SLOPE * v; }

// ---------------------------------------------------------------------------
// CSR build: init -> detect -> hist -> scan1 -> scan3 -> scatter
// ---------------------------------------------------------------------------
__global__ void init_kernel() {
    int i = blockIdx.x * blockDim.x + threadIdx.x;
    if (i < NN) { g_deg[i] = 1; g_cur[i] = 0; }   // deg=1: self-loop
    if (i == 0) { g_not64 = 0; g_off[NN] = EPE; }
}

__global__ void detect_kernel(const long long* __restrict__ ei) {
    int i = blockIdx.x * blockDim.x + threadIdx.x;
    if (i < DETECT_SAMPLES) {
        long long v = ei[i];
        if (v < 0 || v >= NN) g_not64 = 1;
    }
}

__global__ void hist_kernel(const void* __restrict__ ei) {
    int i = blockIdx.x * blockDim.x + threadIdx.x;
    if (i >= EE) return;
    int d = (g_not64 == 0) ? (int)((const long long*)ei)[EE + i]
                           : ((const int*)ei)[EE + i];
    atomicAdd(&g_deg[d], 1);
}

__global__ void scan1_kernel() {          // per-block sums of g_deg
    __shared__ int sm[1024];
    int t = threadIdx.x, i = blockIdx.x * 1024 + t;
    sm[t] = (i < NN) ? g_deg[i] : 0;
    __syncthreads();
    for (int ofs = 512; ofs > 0; ofs >>= 1) {
        if (t < ofs) sm[t] += sm[t + ofs];
        __syncthreads();
    }
    if (t == 0) g_bsum[blockIdx.x] = sm[0];
}

__global__ void scan3_kernel() {          // block scan + cross-block base
    __shared__ int sm[1024];
    int t = threadIdx.x, b = blockIdx.x;
    sm[t] = (t < NB && t < b) ? g_bsum[t] : 0;
    __syncthreads();
    for (int ofs = 512; ofs > 0; ofs >>= 1) {
        if (t < ofs) sm[t] += sm[t + ofs];
        __syncthreads();
    }
    int base = sm[0];
    __syncthreads();
    int i = b * 1024 + t;
    int v = (i < NN) ? g_deg[i] : 0;
    sm[t] = v;
    __syncthreads();
    for (int ofs = 1; ofs < 1024; ofs <<= 1) {
        int x = (t >= ofs) ? sm[t - ofs] : 0;
        __syncthreads();
        sm[t] += x;
        __syncthreads();
    }
    if (i < NN) g_off[i] = base + sm[t] - v;
}

__global__ void scatter_kernel(const void* __restrict__ ei) {
    int i = blockIdx.x * blockDim.x + threadIdx.x;
    if (i >= EPE) return;
    int s, d;
    if (i >= EE) { s = d = i - EE; }
    else if (g_not64 == 0) {
        s = (int)((const long long*)ei)[i];
        d = (int)((const long long*)ei)[EE + i];
    } else {
        s = ((const int*)ei)[i];
        d = ((const int*)ei)[EE + i];
    }
    int pos = g_off[d] + atomicAdd(&g_cur[d], 1);
    g_ssrc[pos] = s;
}

// ---------------------------------------------------------------------------
// Dual GEMM, f32x2, LDS-light tiling: 64 rows x 128 cols per block (256 thr),
// 8 rows x 4 cols per thread.  Split outputs Yl (cols<JH) / Yr (cols>=JH).
// ---------------------------------------------------------------------------
__global__ void __launch_bounds__(256)
gemm_dual_kernel(const float* __restrict__ X, int n, int JH,
                 const float* __restrict__ W1, const float* __restrict__ b1,
                 const float* __restrict__ W2, const float* __restrict__ b2,
                 const float* __restrict__ preBias,
                 float* __restrict__ Yl, float* __restrict__ Yr) {
    __shared__ float Wsm[64 * 128];   // [k][col]  32 KB
    __shared__ float Xs[64 * 64];     // [row][k]  16 KB
    const int tid = threadIdx.x;
    const int jt = blockIdx.y;
    const int row0 = blockIdx.x * 64;

#pragma unroll
    for (int t = 0; t < 32; t++) {
        int i = tid + t * 256;
        int k = i >> 7, jj = i & 127;
        int j = jt * 128 + jj;
        Wsm[i] = (j < JH) ? W1[k * JH + j] : W2[k * JH + (j - JH)];
    }
#pragma unroll
    for (int t = 0; t < 4; t++) {
        int i = tid + t * 256;            // float4 index (1024 total)
        int r = i >> 4, kq = (i & 15) * 4;
        int row = row0 + r;
        float4 v = make_float4(0.f, 0.f, 0.f, 0.f);
        if (row < n) {
            v = *(const float4*)&X[(size_t)row * 64 + kq];
            if (preBias) {
                v.x = fmaxf(v.x + preBias[kq + 0], 0.f);
                v.y = fmaxf(v.y + preBias[kq + 1], 0.f);
                v.z = fmaxf(v.z + preBias[kq + 2], 0.f);
                v.w = fmaxf(v.w + preBias[kq + 3], 0.f);
            }
        }
        *(float4*)&Xs[r * 64 + kq] = v;
    }
    __syncthreads();

    const int cg = tid & 31, wrp = tid >> 5;
    const int c0 = cg * 4;
    const int r0 = wrp * 8;

    int j = jt * 128 + c0;
    const float* bb = (j < JH) ? (b1 + j) : (b2 + (j - JH));
    u64 b01 = pack2(bb[0], bb[1]), b23 = pack2(bb[2], bb[3]);
    u64 acc[8][2];
#pragma unroll
    for (int r = 0; r < 8; r++) { acc[r][0] = b01; acc[r][1] = b23; }

#pragma unroll
    for (int kk = 0; kk < 64; kk += 4) {
        ulonglong2 w[4];
#pragma unroll
        for (int q = 0; q < 4; q++)
            w[q] = *(const ulonglong2*)&Wsm[(kk + q) * 128 + c0];
#pragma unroll
        for (int r = 0; r < 8; r++) {
            float4 xv = *(const float4*)&Xs[(r0 + r) * 64 + kk];
            u64 p;
            p = pack2(xv.x, xv.x); acc[r][0] = ffma2(p, w[0].x, acc[r][0]); acc[r][1] = ffma2(p, w[0].y, acc[r][1]);
            p = pack2(xv.y, xv.y); acc[r][0] = ffma2(p, w[1].x, acc[r][0]); acc[r][1] = ffma2(p, w[1].y, acc[r][1]);
            p = pack2(xv.z, xv.z); acc[r][0] = ffma2(p, w[2].x, acc[r][0]); acc[r][1] = ffma2(p, w[2].y, acc[r][1]);
            p = pack2(xv.w, xv.w); acc[r][0] = ffma2(p, w[3].x, acc[r][0]); acc[r][1] = ffma2(p, w[3].y, acc[r][1]);
        }
    }

    float* Yb; int jj;
    if (j < JH) { Yb = Yl; jj = j; } else { Yb = Yr; jj = j - JH; }
#pragma unroll
    for (int r = 0; r < 8; r++) {
        int row = row0 + r0 + r;
        if (row < n) {
            float2 lo = unpack2(acc[r][0]), hi = unpack2(acc[r][1]);
            *(float4*)&Yb[(size_t)row * JH + jj] = make_float4(lo.x, lo.y, hi.x, hi.y);
        }
    }
}

// ---------------------------------------------------------------------------
// Fused layer-1 edge pass: warp per dst, 4-way edge unroll.
// Lane l holds channels {2l, 2l+1}; head h = l>>3 (8 lanes/head).
// ---------------------------------------------------------------------------
__global__ void fused1_kernel(const float* __restrict__ att) {
    int d = blockIdx.x * 8 + (threadIdx.x >> 5);
    if (d >= NN) return;
    int lane = threadIdx.x & 31;

    float2 xr = *(const float2*)(g_xr1 + (size_t)d * 64 + lane * 2);
    float a0 = __ldg(att + lane * 2), a1 = __ldg(att + lane * 2 + 1);

    int e = g_off[d], e1 = g_off[d + 1];
    float acc0 = 0.f, acc1 = 0.f, den = 0.f;

    for (; e + 4 <= e1; e += 4) {
        int s0 = g_ssrc[e], s1 = g_ssrc[e + 1], s2 = g_ssrc[e + 2], s3 = g_ssrc[e + 3];
        float2 x0 = __ldg((const float2*)(g_xl1 + (size_t)s0 * 64 + lane * 2));
        float2 x1 = __ldg((const float2*)(g_xl1 + (size_t)s1 * 64 + lane * 2));
        float2 x2 = __ldg((const float2*)(g_xl1 + (size_t)s2 * 64 + lane * 2));
        float2 x3 = __ldg((const float2*)(g_xl1 + (size_t)s3 * 64 + lane * 2));
        float c0 = lrelu(x0.x + xr.x) * a0 + lrelu(x0.y + xr.y) * a1;
        float c1 = lrelu(x1.x + xr.x) * a0 + lrelu(x1.y + xr.y) * a1;
        float c2 = lrelu(x2.x + xr.x) * a0 + lrelu(x2.y + xr.y) * a1;
        float c3 = lrelu(x3.x + xr.x) * a0 + lrelu(x3.y + xr.y) * a1;
        c0 += __shfl_xor_sync(0xffffffffu, c0, 1);
        c1 += __shfl_xor_sync(0xffffffffu, c1, 1);
        c2 += __shfl_xor_sync(0xffffffffu, c2, 1);
        c3 += __shfl_xor_sync(0xffffffffu, c3, 1);
        c0 += __shfl_xor_sync(0xffffffffu, c0, 2);
        c1 += __shfl_xor_sync(0xffffffffu, c1, 2);
        c2 += __shfl_xor_sync(0xffffffffu, c2, 2);
        c3 += __shfl_xor_sync(0xffffffffu, c3, 2);
        c0 += __shfl_xor_sync(0xffffffffu, c0, 4);
        c1 += __shfl_xor_sync(0xffffffffu, c1, 4);
        c2 += __shfl_xor_sync(0xffffffffu, c2, 4);
        c3 += __shfl_xor_sync(0xffffffffu, c3, 4);
        float e0x = __expf(c0), e1x = __expf(c1), e2x = __expf(c2), e3x = __expf(c3);
        den += e0x + e1x + e2x + e3x;
        acc0 = fmaf(e0x, x0.x, acc0); acc1 = fmaf(e0x, x0.y, acc1);
        acc0 = fmaf(e1x, x1.x, acc0); acc1 = fmaf(e1x, x1.y, acc1);
        acc0 = fmaf(e2x, x2.x, acc0); acc1 = fmaf(e2x, x2.y, acc1);
        acc0 = fmaf(e3x, x3.x, acc0); acc1 = fmaf(e3x, x3.y, acc1);
    }
    for (; e < e1; e++) {
        int s0 = g_ssrc[e];
        float2 x0 = __ldg((const float2*)(g_xl1 + (size_t)s0 * 64 + lane * 2));
        float c0 = lrelu(x0.x + xr.x) * a0 + lrelu(x0.y + xr.y) * a1;
        c0 += __shfl_xor_sync(0xffffffffu, c0, 1);
        c0 += __shfl_xor_sync(0xffffffffu, c0, 2);
        c0 += __shfl_xor_sync(0xffffffffu, c0, 4);
        float e0x = __expf(c0);
        den += e0x;
        acc0 = fmaf(e0x, x0.x, acc0);
        acc1 = fmaf(e0x, x0.y, acc1);
    }
    float inv = 1.f / (den + 1e-16f);
    *(float2*)(g_agg1 + (size_t)d * 64 + lane * 2) = make_float2(acc0 * inv, acc1 * inv);
}

// ---------------------------------------------------------------------------
// Fused layer-2 edge pass + head-mean + bias + relu -> final output.
// Warp per dst, 4-way edge unroll; lane l holds channels {8l..8l+7} of 256.
// ---------------------------------------------------------------------------
__device__ __forceinline__ float score8(const float4& v0, const float4& v1,
                                        const float4& xr0, const float4& xr1,
                                        const float4& at0, const float4& at1) {
    return lrelu(v0.x + xr0.x) * at0.x + lrelu(v0.y + xr0.y) * at0.y
         + lrelu(v0.z + xr0.z) * at0.z + lrelu(v0.w + xr0.w) * at0.w
         + lrelu(v1.x + xr1.x) * at1.x + lrelu(v1.y + xr1.y) * at1.y
         + lrelu(v1.z + xr1.z) * at1.z + lrelu(v1.w + xr1.w) * at1.w;
}

__device__ __forceinline__ void acc8(float* acc, float ex,
                                     const float4& v0, const float4& v1) {
    acc[0] = fmaf(ex, v0.x, acc[0]); acc[1] = fmaf(ex, v0.y, acc[1]);
    acc[2] = fmaf(ex, v0.z, acc[2]); acc[3] = fmaf(ex, v0.w, acc[3]);
    acc[4] = fmaf(ex, v1.x, acc[4]); acc[5] = fmaf(ex, v1.y, acc[5]);
    acc[6] = fmaf(ex, v1.z, acc[6]); acc[7] = fmaf(ex, v1.w, acc[7]);
}

__global__ void fused2_kernel(const float* __restrict__ att,
                              const float* __restrict__ bo2,
                              float* __restrict__ out) {
    int d = blockIdx.x * 8 + (threadIdx.x >> 5);
    if (d >= NN) return;
    int lane = threadIdx.x & 31;

    const float4* xrp = (const float4*)(g_xr2 + (size_t)d * 256 + lane * 8);
    float4 xr0 = xrp[0], xr1 = xrp[1];
    float4 at0 = *(const float4*)(att + lane * 8);
    float4 at1 = *(const float4*)(att + lane * 8 + 4);

    float acc[8];
#pragma unroll
    for (int q = 0; q < 8; q++) acc[q] = 0.f;
    float den = 0.f;

    int e = g_off[d], e1 = g_off[d + 1];

    for (; e + 4 <= e1; e += 4) {
        int s0 = g_ssrc[e], s1 = g_ssrc[e + 1], s2 = g_ssrc[e + 2], s3 = g_ssrc[e + 3];
        const float4* p0 = (const float4*)(g_xl2 + (size_t)s0 * 256 + lane * 8);
        const float4* p1 = (const float4*)(g_xl2 + (size_t)s1 * 256 + lane * 8);
        const float4* p2 = (const float4*)(g_xl2 + (size_t)s2 * 256 + lane * 8);
        const float4* p3 = (const float4*)(g_xl2 + (size_t)s3 * 256 + lane * 8);
        float4 a0 = __ldg(p0), a1 = __ldg(p0 + 1);
        float4 b0 = __ldg(p1), b1 = __ldg(p1 + 1);
        float4 c0v = __ldg(p2), c1v = __ldg(p2 + 1);
        float4 d0 = __ldg(p3), d1 = __ldg(p3 + 1);

        float c0 = score8(a0, a1, xr0, xr1, at0, at1);
        float c1 = score8(b0, b1, xr0, xr1, at0, at1);
        float c2 = score8(c0v, c1v, xr0, xr1, at0, at1);
        float c3 = score8(d0, d1, xr0, xr1, at0, at1);
        c0 += __shfl_xor_sync(0xffffffffu, c0, 1);
        c1 += __shfl_xor_sync(0xffffffffu, c1, 1);
        c2 += __shfl_xor_sync(0xffffffffu, c2, 1);
        c3 += __shfl_xor_sync(0xffffffffu, c3, 1);
        c0 += __shfl_xor_sync(0xffffffffu, c0, 2);
        c1 += __shfl_xor_sync(0xffffffffu, c1, 2);
        c2 += __shfl_xor_sync(0xffffffffu, c2, 2);
        c3 += __shfl_xor_sync(0xffffffffu, c3, 2);
        c0 += __shfl_xor_sync(0xffffffffu, c0, 4);
        c1 += __shfl_xor_sync(0xffffffffu, c1, 4);
        c2 += __shfl_xor_sync(0xffffffffu, c2, 4);
        c3 += __shfl_xor_sync(0xffffffffu, c3, 4);
        float e0x = __expf(c0), e1x = __expf(c1), e2x = __expf(c2), e3x = __expf(c3);
        den += e0x + e1x + e2x + e3x;
        acc8(acc, e0x, a0, a1);
        acc8(acc, e1x, b0, b1);
        acc8(acc, e2x, c0v, c1v);
        acc8(acc, e3x, d0, d1);
    }
    for (; e < e1; e++) {
        int s0 = g_ssrc[e];
        const float4* p0 = (const float4*)(g_xl2 + (size_t)s0 * 256 + lane * 8);
        float4 a0 = __ldg(p0), a1 = __ldg(p0 + 1);
        float c0 = score8(a0, a1, xr0, xr1, at0, at1);
        c0 += __shfl_xor_sync(0xffffffffu, c0, 1);
        c0 += __shfl_xor_sync(0xffffffffu, c0, 2);
        c0 += __shfl_xor_sync(0xffffffffu, c0, 4);
        float e0x = __expf(c0);
        den += e0x;
        acc8(acc, e0x, a0, a1);
    }

    float inv = 1.f / (den + 1e-16f);
    float nv[8];
#pragma unroll
    for (int q = 0; q < 8; q++) {
        float v = acc[q] * inv;
        v += __shfl_xor_sync(0xffffffffu, v, 8);
        v += __shfl_xor_sync(0xffffffffu, v, 16);
        nv[q] = v;
    }
    if (lane < 8) {
        int c = lane * 8;
        float4 o0, o1;
        o0.x = fmaxf(0.25f * nv[0] + __ldg(bo2 + c + 0), 0.f);
        o0.y = fmaxf(0.25f * nv[1] + __ldg(bo2 + c + 1), 0.f);
        o0.z = fmaxf(0.25f * nv[2] + __ldg(bo2 + c + 2), 0.f);
        o0.w = fmaxf(0.25f * nv[3] + __ldg(bo2 + c + 3), 0.f);
        o1.x = fmaxf(0.25f * nv[4] + __ldg(bo2 + c + 4), 0.f);
        o1.y = fmaxf(0.25f * nv[5] + __ldg(bo2 + c + 5), 0.f);
        o1.z = fmaxf(0.25f * nv[6] + __ldg(bo2 + c + 6), 0.f);
        o1.w = fmaxf(0.25f * nv[7] + __ldg(bo2 + c + 7), 0.f);
        *(float4*)(out + (size_t)d * 64 + c) = o0;
        *(float4*)(out + (size_t)d * 64 + c + 4) = o1;
    }
}

// ---------------------------------------------------------------------------
// Launch
// ---------------------------------------------------------------------------
extern "C" void kernel_launch(void* const* d_in, const int* in_sizes, int n_in,
                              void* d_out, int out_size) {
    const float* x   = (const float*)d_in[0];
    const void*  ei  = d_in[1];
    // d_in[2]: frame_mask (unused)
    const float* Wl1 = (const float*)d_in[3];
    const float* bl1 = (const float*)d_in[4];
    const float* Wr1 = (const float*)d_in[5];
    const float* br1 = (const float*)d_in[6];
    const float* att1 = (const float*)d_in[7];
    const float* bo1 = (const float*)d_in[8];
    const float* Wl2 = (const float*)d_in[9];
    const float* bl2 = (const float*)d_in[10];
    const float* Wr2 = (const float*)d_in[11];
    const float* br2 = (const float*)d_in[12];
    const float* att2 = (const float*)d_in[13];
    const float* bo2 = (const float*)d_in[14];
    float* out = (float*)d_out;

    float *p_xl1, *p_xr1, *p_agg1, *p_xl2, *p_xr2;
    cudaGetSymbolAddress((void**)&p_xl1, g_xl1);
    cudaGetSymbolAddress((void**)&p_xr1, g_xr1);
    cudaGetSymbolAddress((void**)&p_agg1, g_agg1);
    cudaGetSymbolAddress((void**)&p_xl2, g_xl2);
    cudaGetSymbolAddress((void**)&p_xr2, g_xr2);

    // CSR build (sorted by dst)
    init_kernel<<<(NN + 255) / 256, 256>>>();
    detect_kernel<<<(DETECT_SAMPLES + 255) / 256, 256>>>((const long long*)ei);
    hist_kernel<<<(EE + 255) / 256, 256>>>(ei);
    scan1_kernel<<<NB, 1024>>>();
    scan3_kernel<<<NB, 1024>>>();
    scatter_kernel<<<(EPE + 255) / 256, 256>>>(ei);

    // Layer 1
    {
        dim3 grid((NN + 63) / 64, 1);
        gemm_dual_kernel<<<grid, 256>>>(x, NN, 64, Wl1, bl1, Wr1, br1, nullptr,
                                        p_xl1, p_xr1);
    }
    fused1_kernel<<<(NN + 7) / 8, 256>>>(att1);

    // Layer 2 (relu(agg1 + bo1) folded into GEMM input load)
    {
        dim3 grid((NN + 63) / 64, 4);
        gemm_dual_kernel<<<grid, 256>>>(p_agg1, NN, 256, Wl2, bl2, Wr2, br2, bo1,
                                        p_xl2, p_xr2);
    }
    fused2_kernel<<<(NN + 7) / 8, 256>>>(att2, bo2, out);
}